// round 2
// baseline (speedup 1.0000x reference)
#include <cuda_runtime.h>
#include <float.h>
#include <stdint.h>

// Morphological dilation2d (max-plus conv):
//   out[b,o,h,w] = max_{c,i,j}( x_pad[b,c,h+i,w+j] + wt[o,c,i,j] ),  zero padding participates.
// B=C=O=4, H=W=1024, k=5, pad=2.
//
// Issue-bound kernel: 100 FADD (fma pipe) + 100 FMNMX (alu pipe) per output,
// interleaved to saturate both pipes at 1 ipc/SMSP.

#define TH 32
#define TW 64
#define TPT 8               // w-outputs per thread
#define XROWS (TH + 4)      // 36
#define XCOLS (TW + 4)      // 68
#define XSTRIDE 72          // padded: 288B per row, 16B aligned for LDS.128

__global__ __launch_bounds__(256, 2)
void Morphology_84602265797171_kernel(const float* __restrict__ x,
                                      const float* __restrict__ wt,
                                      float* __restrict__ out) {
    __shared__ float xs[4][XROWS][XSTRIDE];       // 41472 B
    __shared__ float4 wsm[100];                   // [(c*5+i)*5+j] -> {o0,o1,o2,o3}

    const int tid = threadIdx.x;
    const int b  = blockIdx.z;
    const int h0 = blockIdx.y * TH;
    const int w0 = blockIdx.x * TW;

    // --- prepack weights: wt layout [o][c][i][j] -> wsm[cij] = (o0,o1,o2,o3) ---
    if (tid < 100) {
        float v0 = wt[tid];          // o=0, cij=tid
        float v1 = wt[tid + 100];
        float v2 = wt[tid + 200];
        float v3 = wt[tid + 300];
        wsm[tid] = make_float4(v0, v1, v2, v3);
    }

    // --- load x tile (all 4 c) with halo; zero-fill OOB (zero padding) ---
    const float* xb = x + (size_t)b * 4 * 1024 * 1024;
    for (int idx = tid; idx < 4 * XROWS * XCOLS; idx += 256) {
        int c   = idx / (XROWS * XCOLS);
        int rem = idx % (XROWS * XCOLS);
        int r   = rem / XCOLS;
        int col = rem % XCOLS;
        int gh  = h0 - 2 + r;
        int gw  = w0 - 2 + col;
        float v = 0.0f;
        if ((unsigned)gh < 1024u && (unsigned)gw < 1024u)
            v = xb[(size_t)c * 1024 * 1024 + (size_t)gh * 1024 + gw];
        xs[c][r][col] = v;
    }
    __syncthreads();

    const int th = tid >> 3;            // 0..31
    const int tw = (tid & 7) * TPT;     // 0..56 (multiple of 8 -> 32B-aligned LDS.128)

    // acc[o][t]
    float a0[TPT], a1[TPT], a2[TPT], a3[TPT];
    #pragma unroll
    for (int t = 0; t < TPT; t++) {
        a0[t] = -FLT_MAX; a1[t] = -FLT_MAX; a2[t] = -FLT_MAX; a3[t] = -FLT_MAX;
    }

    #pragma unroll 1
    for (int ci = 0; ci < 20; ci++) {           // ci = c*5 + i
        const int c = ci / 5;
        const int i = ci % 5;
        const float* row = &xs[c][th + i][tw];

        // 12 x samples for this (c,i): three 16B loads
        float xv[12];
        {
            float4 p0 = *(const float4*)(row + 0);
            float4 p1 = *(const float4*)(row + 4);
            float4 p2 = *(const float4*)(row + 8);
            xv[0]=p0.x; xv[1]=p0.y; xv[2]=p0.z;  xv[3]=p0.w;
            xv[4]=p1.x; xv[5]=p1.y; xv[6]=p1.z;  xv[7]=p1.w;
            xv[8]=p2.x; xv[9]=p2.y; xv[10]=p2.z; xv[11]=p2.w;
        }
        const float4* wr = &wsm[ci * 5];

        #pragma unroll
        for (int j = 0; j < 5; j++) {
            float4 w = wr[j];                    // broadcast LDS.128
            #pragma unroll
            for (int t = 0; t < TPT; t++) {
                float xvt = xv[t + j];
                a0[t] = fmaxf(a0[t], xvt + w.x);
                a1[t] = fmaxf(a1[t], xvt + w.y);
                a2[t] = fmaxf(a2[t], xvt + w.z);
                a3[t] = fmaxf(a3[t], xvt + w.w);
            }
        }
    }

    // --- store: float4 x2 per output channel ---
    const size_t plane = (size_t)1024 * 1024;
    float* ob = out + (size_t)b * 4 * plane + (size_t)(h0 + th) * 1024 + (w0 + tw);

    *(float4*)(ob + 0 * plane)     = make_float4(a0[0], a0[1], a0[2], a0[3]);
    *(float4*)(ob + 0 * plane + 4) = make_float4(a0[4], a0[5], a0[6], a0[7]);
    *(float4*)(ob + 1 * plane)     = make_float4(a1[0], a1[1], a1[2], a1[3]);
    *(float4*)(ob + 1 * plane + 4) = make_float4(a1[4], a1[5], a1[6], a1[7]);
    *(float4*)(ob + 2 * plane)     = make_float4(a2[0], a2[1], a2[2], a2[3]);
    *(float4*)(ob + 2 * plane + 4) = make_float4(a2[4], a2[5], a2[6], a2[7]);
    *(float4*)(ob + 3 * plane)     = make_float4(a3[0], a3[1], a3[2], a3[3]);
    *(float4*)(ob + 3 * plane + 4) = make_float4(a3[4], a3[5], a3[6], a3[7]);
}

extern "C" void kernel_launch(void* const* d_in, const int* in_sizes, int n_in,
                              void* d_out, int out_size) {
    const float* x  = (const float*)d_in[0];   // (4,4,1024,1024) f32
    const float* wt = (const float*)d_in[1];   // (4,4,5,5) f32
    float* out = (float*)d_out;                // (4,4,1024,1024) f32

    dim3 grid(1024 / TW, 1024 / TH, 4);        // (16, 32, 4)
    dim3 block(256);
    Morphology_84602265797171_kernel<<<grid, block>>>(x, wt, out);
}

// round 3
// speedup vs baseline: 1.1267x; 1.1267x over previous
#include <cuda_runtime.h>
#include <float.h>
#include <stdint.h>

// Morphological dilation2d (max-plus conv):
//   out[b,o,h,w] = max_{c,i,j}( x_pad[b,c,h+i,w+j] + wt[o,c,i,j] ),  zero padding participates.
// B=C=O=4, H=W=1024, k=5, pad=2.
//
// R3: occupancy-bound fix. TW 64->32, TPT 8->4, regs capped at 64 via
// __launch_bounds__(256,4): 4 CTAs/SM = 32 warps (occ 50%), smem ~25KB.

#define TH 32
#define TW 32
#define TPT 4               // w-outputs per thread
#define XROWS (TH + 4)      // 36
#define XCOLS (TW + 4)      // 36
#define XSTRIDE 40          // padded: 160B/row, 16B-aligned, conflict-friendly

__global__ __launch_bounds__(256, 4)
void Morphology_84602265797171_kernel(const float* __restrict__ x,
                                      const float* __restrict__ wt,
                                      float* __restrict__ out) {
    __shared__ float xs[4][XROWS][XSTRIDE];       // 23040 B
    __shared__ float4 wsm[100];                   // [(c*5+i)*5+j] -> {o0,o1,o2,o3}

    const int tid = threadIdx.x;
    const int b  = blockIdx.z;
    const int h0 = blockIdx.y * TH;
    const int w0 = blockIdx.x * TW;

    // --- prepack weights: wt layout [o][c][i][j] -> wsm[cij] = (o0,o1,o2,o3) ---
    if (tid < 100) {
        wsm[tid] = make_float4(wt[tid], wt[tid + 100], wt[tid + 200], wt[tid + 300]);
    }

    // --- load x tile (all 4 c) with halo; zero-fill OOB (zero padding) ---
    const float* xb = x + (size_t)b * 4 * 1024 * 1024;
    for (int idx = tid; idx < 4 * XROWS * XCOLS; idx += 256) {
        int c   = idx / (XROWS * XCOLS);
        int rem = idx % (XROWS * XCOLS);
        int r   = rem / XCOLS;
        int col = rem % XCOLS;
        int gh  = h0 - 2 + r;
        int gw  = w0 - 2 + col;
        float v = 0.0f;
        if ((unsigned)gh < 1024u && (unsigned)gw < 1024u)
            v = xb[(size_t)c * 1024 * 1024 + (size_t)gh * 1024 + gw];
        xs[c][r][col] = v;
    }
    __syncthreads();

    const int th = tid >> 3;            // 0..31  output row
    const int tw = (tid & 7) * TPT;     // 0..28  first output col (16B-aligned reads)

    float a0[TPT], a1[TPT], a2[TPT], a3[TPT];
    #pragma unroll
    for (int t = 0; t < TPT; t++) {
        a0[t] = -FLT_MAX; a1[t] = -FLT_MAX; a2[t] = -FLT_MAX; a3[t] = -FLT_MAX;
    }

    #pragma unroll 1
    for (int ci = 0; ci < 20; ci++) {           // ci = c*5 + i
        const int c = ci / 5;
        const int i = ci % 5;
        const float* row = &xs[c][th + i][tw];

        // 8 x samples for this (c,i): two 16B loads
        float xv[8];
        {
            float4 p0 = *(const float4*)(row + 0);
            float4 p1 = *(const float4*)(row + 4);
            xv[0]=p0.x; xv[1]=p0.y; xv[2]=p0.z; xv[3]=p0.w;
            xv[4]=p1.x; xv[5]=p1.y; xv[6]=p1.z; xv[7]=p1.w;
        }
        const float4* wr = &wsm[ci * 5];

        #pragma unroll
        for (int j = 0; j < 5; j++) {
            float4 w = wr[j];                    // uniform LDS.128 (broadcast)
            #pragma unroll
            for (int t = 0; t < TPT; t++) {
                float xvt = xv[t + j];
                a0[t] = fmaxf(a0[t], xvt + w.x);
                a1[t] = fmaxf(a1[t], xvt + w.y);
                a2[t] = fmaxf(a2[t], xvt + w.z);
                a3[t] = fmaxf(a3[t], xvt + w.w);
            }
        }
    }

    // --- store: one float4 per output channel ---
    const size_t plane = (size_t)1024 * 1024;
    float* ob = out + (size_t)b * 4 * plane + (size_t)(h0 + th) * 1024 + (w0 + tw);

    *(float4*)(ob + 0 * plane) = make_float4(a0[0], a0[1], a0[2], a0[3]);
    *(float4*)(ob + 1 * plane) = make_float4(a1[0], a1[1], a1[2], a1[3]);
    *(float4*)(ob + 2 * plane) = make_float4(a2[0], a2[1], a2[2], a2[3]);
    *(float4*)(ob + 3 * plane) = make_float4(a3[0], a3[1], a3[2], a3[3]);
}

extern "C" void kernel_launch(void* const* d_in, const int* in_sizes, int n_in,
                              void* d_out, int out_size) {
    const float* x  = (const float*)d_in[0];   // (4,4,1024,1024) f32
    const float* wt = (const float*)d_in[1];   // (4,4,5,5) f32
    float* out = (float*)d_out;                // (4,4,1024,1024) f32

    dim3 grid(1024 / TW, 1024 / TH, 4);        // (32, 32, 4)
    dim3 block(256);
    Morphology_84602265797171_kernel<<<grid, block>>>(x, wt, out);
}

// round 4
// speedup vs baseline: 1.9497x; 1.7304x over previous
#include <cuda_runtime.h>
#include <cuda_fp16.h>
#include <float.h>
#include <stdint.h>

// Morphological dilation2d (max-plus conv):
//   out[b,o,h,w] = max_{c,i,j}( x_pad[b,c,h+i,w+j] + wt[o,c,i,j] ),  zero padding participates.
// B=C=O=4, H=W=1024, k=5, pad=2.
//
// R4: fp16x2 packed math. Pack output channels (o0,o1)/(o2,o3) into half2;
// x stored in smem as DUPLICATED half2 (v,v) so every x operand is one aligned
// LDS.32. Per output: ~50 HADD2 + 50 HMNMX2 slots instead of 100 FADD + 100
// FMNMX -> ~2x fewer issue slots (the measured binding resource).

#define TH 32
#define TW 32
#define TPT 4               // w-outputs per thread
#define XROWS (TH + 4)      // 36
#define XCOLS (TW + 4)      // 36
#define XSTRIDE 41          // odd 4B-word stride: rows land in disjoint bank residue classes

__global__ __launch_bounds__(256, 5)
void Morphology_84602265797171_kernel(const float* __restrict__ x,
                                      const float* __restrict__ wt,
                                      float* __restrict__ out) {
    __shared__ half2 xs[4][XROWS][XSTRIDE];            // dup pairs (v,v); 23.6 KB
    __shared__ __align__(16) half2 wsm[200];           // [cij*2+p]: p0=(o0,o1), p1=(o2,o3)

    const int tid = threadIdx.x;
    const int b  = blockIdx.z;
    const int h0 = blockIdx.y * TH;
    const int w0 = blockIdx.x * TW;

    // --- prepack weights: wt layout [o][c][i][j], cij = (c*5+i)*5+j ---
    if (tid < 100) {
        float v0 = wt[tid];
        float v1 = wt[tid + 100];
        float v2 = wt[tid + 200];
        float v3 = wt[tid + 300];
        wsm[tid * 2 + 0] = __floats2half2_rn(v0, v1);
        wsm[tid * 2 + 1] = __floats2half2_rn(v2, v3);
    }

    // --- load x tile (all 4 c) with halo; zero-fill OOB; store as dup half2 ---
    const float* xb = x + (size_t)b * 4 * 1024 * 1024;
    for (int idx = tid; idx < 4 * XROWS * XCOLS; idx += 256) {
        int c   = idx / (XROWS * XCOLS);
        int rem = idx % (XROWS * XCOLS);
        int r   = rem / XCOLS;
        int col = rem % XCOLS;
        int gh  = h0 - 2 + r;
        int gw  = w0 - 2 + col;
        float v = 0.0f;
        if ((unsigned)gh < 1024u && (unsigned)gw < 1024u)
            v = xb[(size_t)c * 1024 * 1024 + (size_t)gh * 1024 + gw];
        half hv = __float2half_rn(v);
        xs[c][r][col] = __half2half2(hv);
    }
    __syncthreads();

    const int th = tid >> 3;            // 0..31  output row
    const int tw = (tid & 7) * TPT;     // 0..28  first output col

    half2 acc01[TPT], acc23[TPT];
    const half2 NEG = __half2half2(__float2half_rn(-60000.0f));
    #pragma unroll
    for (int t = 0; t < TPT; t++) { acc01[t] = NEG; acc23[t] = NEG; }

    #pragma unroll 1
    for (int c = 0; c < 4; c++) {
        #pragma unroll
        for (int i = 0; i < 5; i++) {
            const half2* row = &xs[c][th + i][tw];
            // 8 broadcast x pairs for this (c,i): eight LDS.32
            half2 xv[TPT + 4];
            #pragma unroll
            for (int y = 0; y < TPT + 4; y++) xv[y] = row[y];

            const half2* wr = &wsm[((c * 5 + i) * 5) * 2];
            #pragma unroll
            for (int j = 0; j < 5; j++) {
                half2 w01 = wr[2 * j + 0];      // adjacent -> LDS.64 broadcast
                half2 w23 = wr[2 * j + 1];
                #pragma unroll
                for (int t = 0; t < TPT; t++) {
                    half2 xp = xv[t + j];
                    acc01[t] = __hmax2(acc01[t], __hadd2(xp, w01));
                    acc23[t] = __hmax2(acc23[t], __hadd2(xp, w23));
                }
            }
        }
    }

    // --- epilogue: unpack to fp32 and store one float4 per output channel ---
    float a0[TPT], a1[TPT], a2[TPT], a3[TPT];
    #pragma unroll
    for (int t = 0; t < TPT; t++) {
        float2 f01 = __half22float2(acc01[t]);
        float2 f23 = __half22float2(acc23[t]);
        a0[t] = f01.x; a1[t] = f01.y; a2[t] = f23.x; a3[t] = f23.y;
    }
    const size_t plane = (size_t)1024 * 1024;
    float* ob = out + (size_t)b * 4 * plane + (size_t)(h0 + th) * 1024 + (w0 + tw);

    *(float4*)(ob + 0 * plane) = make_float4(a0[0], a0[1], a0[2], a0[3]);
    *(float4*)(ob + 1 * plane) = make_float4(a1[0], a1[1], a1[2], a1[3]);
    *(float4*)(ob + 2 * plane) = make_float4(a2[0], a2[1], a2[2], a2[3]);
    *(float4*)(ob + 3 * plane) = make_float4(a3[0], a3[1], a3[2], a3[3]);
}

extern "C" void kernel_launch(void* const* d_in, const int* in_sizes, int n_in,
                              void* d_out, int out_size) {
    const float* x  = (const float*)d_in[0];   // (4,4,1024,1024) f32
    const float* wt = (const float*)d_in[1];   // (4,4,5,5) f32
    float* out = (float*)d_out;                // (4,4,1024,1024) f32

    dim3 grid(1024 / TW, 1024 / TH, 4);        // (32, 32, 4)
    dim3 block(256);
    Morphology_84602265797171_kernel<<<grid, block>>>(x, wt, out);
}